// round 1
// baseline (speedup 1.0000x reference)
#include <cuda_runtime.h>
#include <math.h>

// Problem constants
#define Bc 1024   // batch
#define Tc 40     // timesteps
#define Ec 512    // embed dim
#define Hc 1024   // hidden
#define Lc 256    // latent out
#define Ac 2048   // feature dim

// ---------------- scratch (device globals, no allocation) ----------------
__device__ float g_Wih0[Hc * Ac];     // 8 MB normalized init_h weight
__device__ float g_Wic0[Hc * Ac];     // 8 MB normalized init_c weight
__device__ float g_Wmu [Lc * Hc];     // 1 MB
__device__ float g_Ws2 [Lc * Hc];     // 1 MB
__device__ float g_h    [Bc * Hc];    // 4 MB hidden state
__device__ float g_c    [Bc * Hc];    // 4 MB cell state
__device__ float g_hlast[Bc * Hc];    // 4 MB gathered last hidden
__device__ float g_gates[Bc * 4 * Hc];// 16 MB gate buffer

// ---------------- weight norm: W[r,c] = g[r] * v[r,c] / ||v[r,:]|| ----------------
__global__ void wn_kernel(const float* __restrict__ v, const float* __restrict__ g,
                          float* __restrict__ W, int cols) {
    int r = blockIdx.x;
    const float* vr = v + (size_t)r * cols;
    float s = 0.f;
    for (int c = threadIdx.x; c < cols; c += blockDim.x) { float x = vr[c]; s += x * x; }
    __shared__ float sh[32];
    for (int o = 16; o > 0; o >>= 1) s += __shfl_down_sync(0xffffffffu, s, o);
    if ((threadIdx.x & 31) == 0) sh[threadIdx.x >> 5] = s;
    __syncthreads();
    if (threadIdx.x < 32) {
        float t = (threadIdx.x < (blockDim.x >> 5)) ? sh[threadIdx.x] : 0.f;
        for (int o = 16; o > 0; o >>= 1) t += __shfl_down_sync(0xffffffffu, t, o);
        if (threadIdx.x == 0) sh[0] = t;
    }
    __syncthreads();
    float scale = g[r] / sqrtf(sh[0]);
    float* Wr = W + (size_t)r * cols;
    for (int c = threadIdx.x; c < cols; c += blockDim.x) Wr[c] = vr[c] * scale;
}

// ---------------- generic C[m,n] = sum_k A[m,k]*W[n,k] + bias[n] ----------------
// Requires M%128==0, N%128==0, K%16==0.
__global__ void __launch_bounds__(256) gemm_tn_bias(
    const float* __restrict__ A, const float* __restrict__ W,
    const float* __restrict__ bias, float* __restrict__ C,
    int M, int N, int K)
{
    __shared__ __align__(16) float As[16][128];
    __shared__ __align__(16) float Bs[16][128];
    int bm = blockIdx.y * 128, bn = blockIdx.x * 128;
    int tid = threadIdx.x;
    int tx = tid & 15, ty = tid >> 4;
    int lr = tid >> 2;          // 0..63
    int lc = (tid & 3) << 2;    // 0,4,8,12

    float acc[8][8];
#pragma unroll
    for (int i = 0; i < 8; i++)
#pragma unroll
        for (int j = 0; j < 8; j++) acc[i][j] = 0.f;

    for (int k0 = 0; k0 < K; k0 += 16) {
#pragma unroll
        for (int s = 0; s < 2; s++) {
            int m = lr + s * 64;
            float4 va = *(const float4*)(A + (size_t)(bm + m) * K + k0 + lc);
            As[lc + 0][m] = va.x; As[lc + 1][m] = va.y;
            As[lc + 2][m] = va.z; As[lc + 3][m] = va.w;
            float4 vb = *(const float4*)(W + (size_t)(bn + m) * K + k0 + lc);
            Bs[lc + 0][m] = vb.x; Bs[lc + 1][m] = vb.y;
            Bs[lc + 2][m] = vb.z; Bs[lc + 3][m] = vb.w;
        }
        __syncthreads();
#pragma unroll
        for (int kk = 0; kk < 16; kk++) {
            float a[8], b[8];
            *(float4*)(a)     = *(const float4*)(&As[kk][ty * 8]);
            *(float4*)(a + 4) = *(const float4*)(&As[kk][ty * 8 + 4]);
            *(float4*)(b)     = *(const float4*)(&Bs[kk][tx * 8]);
            *(float4*)(b + 4) = *(const float4*)(&Bs[kk][tx * 8 + 4]);
#pragma unroll
            for (int i = 0; i < 8; i++)
#pragma unroll
                for (int j = 0; j < 8; j++) acc[i][j] += a[i] * b[j];
        }
        __syncthreads();
    }

    float bb[8];
#pragma unroll
    for (int j = 0; j < 8; j++) bb[j] = bias[bn + tx * 8 + j];
#pragma unroll
    for (int i = 0; i < 8; i++) {
        int m = bm + ty * 8 + i;
        float* Crow = C + (size_t)m * N + bn + tx * 8;
#pragma unroll
        for (int j = 0; j < 8; j++) Crow[j] = acc[i][j] + bb[j];
    }
}

// ---------------- per-step fused gate GEMM ----------------
// gates[b,n] = sum_{k<H} h[b,k]*W_hh[n,k] + sum_{k<E} emb(cap[b,t])[k]*W_ih[n,k]
//            + b_ih[n] + b_hh[n]
// M=Bc=1024, N=4096, K=H+E=1536.
__global__ void __launch_bounds__(256) lstm_gate_gemm(
    const float* __restrict__ h, const float* __restrict__ embed,
    const int* __restrict__ cap, int t,
    const float* __restrict__ W_hh, const float* __restrict__ W_ih,
    const float* __restrict__ b_ih, const float* __restrict__ b_hh,
    float* __restrict__ gates)
{
    const int Nn = 4 * Hc;
    __shared__ __align__(16) float As[16][128];
    __shared__ __align__(16) float Bs[16][128];
    __shared__ int stok[128];
    int bm = blockIdx.y * 128, bn = blockIdx.x * 128;
    int tid = threadIdx.x;
    int tx = tid & 15, ty = tid >> 4;
    int lr = tid >> 2;
    int lc = (tid & 3) << 2;

    if (tid < 128) stok[tid] = cap[(size_t)(bm + tid) * Tc + t];
    __syncthreads();

    float acc[8][8];
#pragma unroll
    for (int i = 0; i < 8; i++)
#pragma unroll
        for (int j = 0; j < 8; j++) acc[i][j] = 0.f;

    for (int k0 = 0; k0 < Hc + Ec; k0 += 16) {
        int kk0 = k0 + lc;
#pragma unroll
        for (int s = 0; s < 2; s++) {
            int m = lr + s * 64;
            float4 va;
            if (kk0 < Hc) {
                va = *(const float4*)(h + (size_t)(bm + m) * Hc + kk0);
            } else {
                int tok = stok[m];
                va = *(const float4*)(embed + (size_t)tok * Ec + (kk0 - Hc));
            }
            As[lc + 0][m] = va.x; As[lc + 1][m] = va.y;
            As[lc + 2][m] = va.z; As[lc + 3][m] = va.w;
            int n = bn + m;
            float4 vb;
            if (kk0 < Hc) vb = *(const float4*)(W_hh + (size_t)n * Hc + kk0);
            else          vb = *(const float4*)(W_ih + (size_t)n * Ec + (kk0 - Hc));
            Bs[lc + 0][m] = vb.x; Bs[lc + 1][m] = vb.y;
            Bs[lc + 2][m] = vb.z; Bs[lc + 3][m] = vb.w;
        }
        __syncthreads();
#pragma unroll
        for (int kk = 0; kk < 16; kk++) {
            float a[8], b[8];
            *(float4*)(a)     = *(const float4*)(&As[kk][ty * 8]);
            *(float4*)(a + 4) = *(const float4*)(&As[kk][ty * 8 + 4]);
            *(float4*)(b)     = *(const float4*)(&Bs[kk][tx * 8]);
            *(float4*)(b + 4) = *(const float4*)(&Bs[kk][tx * 8 + 4]);
#pragma unroll
            for (int i = 0; i < 8; i++)
#pragma unroll
                for (int j = 0; j < 8; j++) acc[i][j] += a[i] * b[j];
        }
        __syncthreads();
    }

    float bb[8];
#pragma unroll
    for (int j = 0; j < 8; j++) {
        int n = bn + tx * 8 + j;
        bb[j] = b_ih[n] + b_hh[n];
    }
#pragma unroll
    for (int i = 0; i < 8; i++) {
        int m = bm + ty * 8 + i;
        float* Crow = gates + (size_t)m * Nn + bn + tx * 8;
#pragma unroll
        for (int j = 0; j < 8; j++) Crow[j] = acc[i][j] + bb[j];
    }
}

// ---------------- LSTM cell elementwise + last-step capture ----------------
__global__ void lstm_cell(const float* __restrict__ gates,
                          float* __restrict__ c, float* __restrict__ h,
                          const int* __restrict__ cap_len, int t,
                          float* __restrict__ h_last)
{
    int idx = blockIdx.x * blockDim.x + threadIdx.x;
    if (idx >= Bc * Hc) return;
    int b = idx >> 10;       // /Hc
    int j = idx & (Hc - 1);  // %Hc
    const float* gr = gates + (size_t)b * 4 * Hc;
    float gi = gr[j];
    float gf = gr[j + Hc];
    float gg = gr[j + 2 * Hc];
    float go = gr[j + 3 * Hc];
    float si = 1.f / (1.f + expf(-gi));
    float sf = 1.f / (1.f + expf(-gf));
    float so = 1.f / (1.f + expf(-go));
    float nc = sf * c[idx] + si * tanhf(gg);
    float nh = so * tanhf(nc);
    c[idx] = nc;
    h[idx] = nh;
    if (cap_len[b] - 1 == t) h_last[idx] = nh;
}

// ---------------- launch ----------------
extern "C" void kernel_launch(void* const* d_in, const int* in_sizes, int n_in,
                              void* d_out, int out_size) {
    const int*   cap     = (const int*)  d_in[0];
    const int*   cap_len = (const int*)  d_in[1];
    const float* feat    = (const float*)d_in[2];
    const float* embed   = (const float*)d_in[3];
    const float* W_ih    = (const float*)d_in[4];
    const float* W_hh    = (const float*)d_in[5];
    const float* b_ih    = (const float*)d_in[6];
    const float* b_hh    = (const float*)d_in[7];
    const float* v_ih0   = (const float*)d_in[8];
    const float* g_ih0   = (const float*)d_in[9];
    const float* b_ih0   = (const float*)d_in[10];
    const float* v_ic0   = (const float*)d_in[11];
    const float* g_ic0   = (const float*)d_in[12];
    const float* b_ic0   = (const float*)d_in[13];
    const float* v_mu    = (const float*)d_in[14];
    const float* g_mu    = (const float*)d_in[15];
    const float* b_mu    = (const float*)d_in[16];
    const float* v_s2    = (const float*)d_in[17];
    const float* g_s2    = (const float*)d_in[18];
    const float* b_s2    = (const float*)d_in[19];
    float* out = (float*)d_out;

    float *Wih0, *Wic0, *Wmu, *Ws2, *h, *c, *hlast, *gates;
    cudaGetSymbolAddress((void**)&Wih0,  g_Wih0);
    cudaGetSymbolAddress((void**)&Wic0,  g_Wic0);
    cudaGetSymbolAddress((void**)&Wmu,   g_Wmu);
    cudaGetSymbolAddress((void**)&Ws2,   g_Ws2);
    cudaGetSymbolAddress((void**)&h,     g_h);
    cudaGetSymbolAddress((void**)&c,     g_c);
    cudaGetSymbolAddress((void**)&hlast, g_hlast);
    cudaGetSymbolAddress((void**)&gates, g_gates);

    // 1) weight-norm all four projection matrices
    wn_kernel<<<Hc, 256>>>(v_ih0, g_ih0, Wih0, Ac);
    wn_kernel<<<Hc, 256>>>(v_ic0, g_ic0, Wic0, Ac);
    wn_kernel<<<Lc, 256>>>(v_mu,  g_mu,  Wmu,  Hc);
    wn_kernel<<<Lc, 256>>>(v_s2,  g_s2,  Ws2,  Hc);

    // 2) h0 = feat @ Wih0^T + b_ih0 ; c0 = feat @ Wic0^T + b_ic0
    {
        dim3 grid(Hc / 128, Bc / 128);
        gemm_tn_bias<<<grid, 256>>>(feat, Wih0, b_ih0, h, Bc, Hc, Ac);
        gemm_tn_bias<<<grid, 256>>>(feat, Wic0, b_ic0, c, Bc, Hc, Ac);
    }

    // 3) recurrence
    {
        dim3 ggrid(4 * Hc / 128, Bc / 128);   // (32, 8)
        int cells = Bc * Hc;
        int cblocks = (cells + 255) / 256;
        for (int t = 0; t < Tc; t++) {
            lstm_gate_gemm<<<ggrid, 256>>>(h, embed, cap, t, W_hh, W_ih, b_ih, b_hh, gates);
            lstm_cell<<<cblocks, 256>>>(gates, c, h, cap_len, t, hlast);
        }
    }

    // 4) outputs: mu then sigma2, each [B, L]
    {
        dim3 grid(Lc / 128, Bc / 128);        // (2, 8)
        gemm_tn_bias<<<grid, 256>>>(hlast, Wmu, b_mu, out,            Bc, Lc, Hc);
        gemm_tn_bias<<<grid, 256>>>(hlast, Ws2, b_s2, out + Bc * Lc,  Bc, Lc, Hc);
    }
}

// round 3
// speedup vs baseline: 3.4638x; 3.4638x over previous
#include <cuda_runtime.h>
#include <cstdint>
#include <math.h>

// ---------------- problem constants ----------------
#define Bc 1024   // batch
#define Tc 40     // timesteps
#define Ec 512    // embed dim
#define Hc 1024   // hidden
#define Lc 256    // latent out
#define Ac 2048   // feature dim
#define Vc 30000  // vocab
#define Nw 4096   // 4*H

// ---------------- device scratch (no allocation) ----------------
__device__ float g_Wih0[Hc * Ac];        // weight-normed init_h weight (tf32-rounded)
__device__ float g_Wic0[Hc * Ac];        // weight-normed init_c weight
__device__ float g_Wmu [Lc * Hc];
__device__ float g_Ws2 [Lc * Hc];
__device__ float g_Wp  [Nw * (Hc + Ec)]; // permuted [4j+gate][W_hh | W_ih], tf32-rounded
__device__ float g_pb  [Nw];             // permuted bias b_ih+b_hh
__device__ float g_hbuf[2][Bc * Hc];     // double-buffered hidden (tf32-rounded)
__device__ float g_c   [Bc * Hc];        // cell state (full fp32)
__device__ float g_hl  [Bc * Hc];        // h at last valid step (tf32-rounded)
__device__ float g_embR[Vc * Ec];        // tf32-rounded embedding
__device__ float g_ftR [Bc * Ac];        // tf32-rounded feat_vec

// ---------------- helpers ----------------
__device__ __forceinline__ float to_tf32(float x) {
    float r;
    asm("cvt.rna.tf32.f32 %0, %1;" : "=f"(r) : "f"(x));
    return r;
}
__device__ __forceinline__ uint32_t smem_u32(const void* p) {
    uint32_t a;
    asm("{ .reg .u64 t; cvta.to.shared.u64 t, %1; cvt.u32.u64 %0, t; }" : "=r"(a) : "l"(p));
    return a;
}
#define CP_ASYNC16(dst, src) \
    asm volatile("cp.async.cg.shared.global [%0], [%1], 16;" :: "r"(dst), "l"(src))
#define CP_COMMIT() asm volatile("cp.async.commit_group;" ::: "memory")
#define CP_WAIT3()  asm volatile("cp.async.wait_group 3;" ::: "memory")

__device__ __forceinline__ void mma_tf32(float* d, const uint32_t* a, const uint32_t* b) {
    asm volatile(
        "mma.sync.aligned.m16n8k8.row.col.f32.tf32.tf32.f32 "
        "{%0,%1,%2,%3}, {%4,%5,%6,%7}, {%8,%9}, {%0,%1,%2,%3};"
        : "+f"(d[0]), "+f"(d[1]), "+f"(d[2]), "+f"(d[3])
        : "r"(a[0]), "r"(a[1]), "r"(a[2]), "r"(a[3]), "r"(b[0]), "r"(b[1]));
}

// ---------------- prep kernels ----------------
__global__ void wn_kernel(const float* __restrict__ v, const float* __restrict__ g,
                          float* __restrict__ W, int cols) {
    int r = blockIdx.x;
    const float* vr = v + (size_t)r * cols;
    float s = 0.f;
    for (int c = threadIdx.x; c < cols; c += blockDim.x) { float x = vr[c]; s += x * x; }
    __shared__ float sh[32];
    for (int o = 16; o > 0; o >>= 1) s += __shfl_down_sync(0xffffffffu, s, o);
    if ((threadIdx.x & 31) == 0) sh[threadIdx.x >> 5] = s;
    __syncthreads();
    if (threadIdx.x < 32) {
        float t = (threadIdx.x < (blockDim.x >> 5)) ? sh[threadIdx.x] : 0.f;
        for (int o = 16; o > 0; o >>= 1) t += __shfl_down_sync(0xffffffffu, t, o);
        if (threadIdx.x == 0) sh[0] = t;
    }
    __syncthreads();
    float scale = g[r] / sqrtf(sh[0]);
    float* Wr = W + (size_t)r * cols;
    for (int c = threadIdx.x; c < cols; c += blockDim.x) Wr[c] = to_tf32(vr[c] * scale);
}

__global__ void permute_kernel(const float* __restrict__ Whh, const float* __restrict__ Wih,
                               const float* __restrict__ bih, const float* __restrict__ bhh,
                               float* __restrict__ Wp, float* __restrict__ pb) {
    int n = blockIdx.x;
    int gt = n >> 10, j = n & 1023;
    int np = (j << 2) | gt;
    float* dst = Wp + (size_t)np * (Hc + Ec);
    const float* s1 = Whh + (size_t)n * Hc;
    const float* s2 = Wih + (size_t)n * Ec;
    for (int k = threadIdx.x; k < Hc; k += blockDim.x) dst[k] = to_tf32(s1[k]);
    for (int k = threadIdx.x; k < Ec; k += blockDim.x) dst[Hc + k] = to_tf32(s2[k]);
    if (threadIdx.x == 0) pb[np] = bih[n] + bhh[n];
}

__global__ void round_copy(const float* __restrict__ src, float* __restrict__ dst, int n) {
    int i = blockIdx.x * blockDim.x + threadIdx.x;
    if (i < n) dst[i] = to_tf32(src[i]);
}

// ---------------- mma.sync tf32 GEMM ----------------
// CTA tile 128(M) x 256(N), K in chunks of 32, 4-stage cp.async pipeline.
// MODE 0: C = A*W^T + bias (optional tf32 round of output)
// MODE 1: fused LSTM cell epilogue (N permuted 4j+gate) -> c, h, h_last
static constexpr int A_OFF = 1024;                       // A stage: 128 rows x 36 floats
static constexpr int A_ST  = 128 * 36 * 4;               // 18432
static constexpr int B_OFF = A_OFF + 4 * A_ST;           // 74752; B stage: 256 x 36
static constexpr int B_ST  = 256 * 36 * 4;               // 36864
static constexpr int SMEM_BYTES = B_OFF + 4 * B_ST;      // 222208
static constexpr int GSTRIDE = 264;                      // gate staging row stride (floats)

template <int MODE>
__global__ __launch_bounds__(256, 1)
void tc_gemm(const float* __restrict__ A1, int lda1, int kc1,
             const float* __restrict__ A2, int lda2, int kc2,
             const int* __restrict__ cap, int t,
             const float* __restrict__ Bw, int ldb,
             const float* __restrict__ bias,
             float* __restrict__ C, int ldc, int round_out,
             const int* __restrict__ cap_len,
             float* __restrict__ cst, float* __restrict__ hst,
             float* __restrict__ hlast)
{
    extern __shared__ __align__(1024) char smem[];
    uint32_t sb = smem_u32(smem);
    int tid = threadIdx.x, wid = tid >> 5, lid = tid & 31;
    int g = lid >> 2, tig = lid & 3;
    int warpM = (wid & 1) * 64, warpN = (wid >> 1) * 64;
    int bm = blockIdx.y * 128, bn = blockIdx.x * 256;
    const int NC = kc1 + kc2;
    int* stok = (int*)smem;  // 512 B header

    if (kc2 > 0 && tid < 128) stok[tid] = cap[(size_t)(bm + tid) * Tc + t];
    __syncthreads();

    float acc[4][8][4];
#pragma unroll
    for (int i = 0; i < 4; i++)
#pragma unroll
        for (int j = 0; j < 8; j++)
#pragma unroll
            for (int q = 0; q < 4; q++) acc[i][j][q] = 0.f;

    auto load_chunk = [&](int c, int s) {
        uint32_t aB = sb + A_OFF + s * A_ST;
        uint32_t bB = sb + B_OFF + s * B_ST;
        bool seg1 = (c < kc1);
        int kbase = seg1 ? c * 32 : (c - kc1) * 32;
#pragma unroll
        for (int i = 0; i < 4; i++) {               // A tile: 128 rows x 32 floats
            int seg = tid + i * 256;
            int m = seg >> 3, ch = seg & 7;
            const float* src = seg1
                ? (A1 + (size_t)(bm + m) * lda1 + kbase + ch * 4)
                : (A2 + (size_t)stok[m] * lda2 + kbase + ch * 4);
            CP_ASYNC16(aB + m * 144 + ch * 16, src);
        }
#pragma unroll
        for (int i = 0; i < 8; i++) {               // B tile: 256 rows x 32 floats
            int seg = tid + i * 256;
            int n = seg >> 3, ch = seg & 7;
            CP_ASYNC16(bB + n * 144 + ch * 16,
                       Bw + (size_t)(bn + n) * ldb + c * 32 + ch * 4);
        }
    };

    // prologue: fill 4 stages
    for (int p = 0; p < 4; p++) { load_chunk(p, p); CP_COMMIT(); }

    for (int c = 0; c < NC; c++) {
        int s = c & 3;
        CP_WAIT3();
        __syncthreads();
        const uint32_t* aU = (const uint32_t*)(smem + A_OFF + s * A_ST);
        const uint32_t* bU = (const uint32_t*)(smem + B_OFF + s * B_ST);
#pragma unroll
        for (int kk = 0; kk < 4; kk++) {
            uint32_t afr[4][4], bfr[8][2];
            int kb = kk * 8 + tig;
#pragma unroll
            for (int rb = 0; rb < 4; rb++) {
                int ar = warpM + rb * 16 + g;
                afr[rb][0] = aU[ar * 36 + kb];
                afr[rb][1] = aU[(ar + 8) * 36 + kb];
                afr[rb][2] = aU[ar * 36 + kb + 4];
                afr[rb][3] = aU[(ar + 8) * 36 + kb + 4];
            }
#pragma unroll
            for (int nb = 0; nb < 8; nb++) {
                int br = warpN + nb * 8 + g;
                bfr[nb][0] = bU[br * 36 + kb];
                bfr[nb][1] = bU[br * 36 + kb + 4];
            }
#pragma unroll
            for (int rb = 0; rb < 4; rb++)
#pragma unroll
                for (int nb = 0; nb < 8; nb++)
                    mma_tf32(acc[rb][nb], afr[rb], bfr[nb]);
        }
        __syncthreads();
        if (c + 4 < NC) load_chunk(c + 4, s);
        CP_COMMIT();
    }

    // ---------------- epilogue ----------------
    if (MODE == 0) {
#pragma unroll
        for (int rb = 0; rb < 4; rb++) {
#pragma unroll
            for (int nb = 0; nb < 8; nb++) {
                int col = bn + warpN + nb * 8 + 2 * tig;
                int r0 = bm + warpM + rb * 16 + g;
                float b0 = bias[col], b1 = bias[col + 1];
                float v0 = acc[rb][nb][0] + b0, v1 = acc[rb][nb][1] + b1;
                float v2 = acc[rb][nb][2] + b0, v3 = acc[rb][nb][3] + b1;
                if (round_out) { v0 = to_tf32(v0); v1 = to_tf32(v1); v2 = to_tf32(v2); v3 = to_tf32(v3); }
                *(float2*)(C + (size_t)r0 * ldc + col)       = make_float2(v0, v1);
                *(float2*)(C + (size_t)(r0 + 8) * ldc + col) = make_float2(v2, v3);
            }
        }
    } else {
        // stage gates to smem (reuses pipeline buffers), then fused cell
        float* gsm = (float*)(smem + A_OFF);
#pragma unroll
        for (int rb = 0; rb < 4; rb++) {
#pragma unroll
            for (int nb = 0; nb < 8; nb++) {
                int col = warpN + nb * 8 + 2 * tig;
                int r0 = warpM + rb * 16 + g;
                *(float2*)(gsm + r0 * GSTRIDE + col)       = make_float2(acc[rb][nb][0], acc[rb][nb][1]);
                *(float2*)(gsm + (r0 + 8) * GSTRIDE + col) = make_float2(acc[rb][nb][2], acc[rb][nb][3]);
            }
        }
        __syncthreads();
        for (int idx = tid; idx < 128 * 64; idx += 256) {
            int row = idx >> 6, jl = idx & 63;
            int gm = bm + row;
            int jg = (bn >> 2) + jl;
            float4 gv = *(const float4*)(gsm + row * GSTRIDE + jl * 4);
            int nb4 = bn + jl * 4;
            float gi = gv.x + bias[nb4 + 0];
            float gf = gv.y + bias[nb4 + 1];
            float gg = gv.z + bias[nb4 + 2];
            float go = gv.w + bias[nb4 + 3];
            float si = 1.f / (1.f + expf(-gi));
            float sf = 1.f / (1.f + expf(-gf));
            float so = 1.f / (1.f + expf(-go));
            size_t off = (size_t)gm * Hc + jg;
            float cn = sf * cst[off] + si * tanhf(gg);
            float hn = to_tf32(so * tanhf(cn));      // h is a tf32 GEMM operand next step
            cst[off] = cn;
            hst[off] = hn;
            if (cap_len[gm] - 1 == t) hlast[off] = hn;
        }
    }
}

// ---------------- launch ----------------
extern "C" void kernel_launch(void* const* d_in, const int* in_sizes, int n_in,
                              void* d_out, int out_size) {
    const int*   cap     = (const int*)  d_in[0];
    const int*   cap_len = (const int*)  d_in[1];
    const float* feat    = (const float*)d_in[2];
    const float* embed   = (const float*)d_in[3];
    const float* W_ih    = (const float*)d_in[4];
    const float* W_hh    = (const float*)d_in[5];
    const float* b_ih    = (const float*)d_in[6];
    const float* b_hh    = (const float*)d_in[7];
    const float* v_ih0   = (const float*)d_in[8];
    const float* g_ih0   = (const float*)d_in[9];
    const float* b_ih0   = (const float*)d_in[10];
    const float* v_ic0   = (const float*)d_in[11];
    const float* g_ic0   = (const float*)d_in[12];
    const float* b_ic0   = (const float*)d_in[13];
    const float* v_mu    = (const float*)d_in[14];
    const float* g_mu    = (const float*)d_in[15];
    const float* b_mu    = (const float*)d_in[16];
    const float* v_s2    = (const float*)d_in[17];
    const float* g_s2    = (const float*)d_in[18];
    const float* b_s2    = (const float*)d_in[19];
    float* out = (float*)d_out;

    float *Wih0, *Wic0, *Wmu, *Ws2, *Wp, *pb, *hbuf, *c, *hl, *embR, *ftR;
    cudaGetSymbolAddress((void**)&Wih0, g_Wih0);
    cudaGetSymbolAddress((void**)&Wic0, g_Wic0);
    cudaGetSymbolAddress((void**)&Wmu,  g_Wmu);
    cudaGetSymbolAddress((void**)&Ws2,  g_Ws2);
    cudaGetSymbolAddress((void**)&Wp,   g_Wp);
    cudaGetSymbolAddress((void**)&pb,   g_pb);
    cudaGetSymbolAddress((void**)&hbuf, g_hbuf);
    cudaGetSymbolAddress((void**)&c,    g_c);
    cudaGetSymbolAddress((void**)&hl,   g_hl);
    cudaGetSymbolAddress((void**)&embR, g_embR);
    cudaGetSymbolAddress((void**)&ftR,  g_ftR);

    cudaFuncSetAttribute(tc_gemm<0>, cudaFuncAttributeMaxDynamicSharedMemorySize, SMEM_BYTES);
    cudaFuncSetAttribute(tc_gemm<1>, cudaFuncAttributeMaxDynamicSharedMemorySize, SMEM_BYTES);

    // prep: weight norm (tf32), permute LSTM weights (tf32), round activations
    wn_kernel<<<Hc, 256>>>(v_ih0, g_ih0, Wih0, Ac);
    wn_kernel<<<Hc, 256>>>(v_ic0, g_ic0, Wic0, Ac);
    wn_kernel<<<Lc, 256>>>(v_mu,  g_mu,  Wmu,  Hc);
    wn_kernel<<<Lc, 256>>>(v_s2,  g_s2,  Ws2,  Hc);
    permute_kernel<<<Nw, 256>>>(W_hh, W_ih, b_ih, b_hh, Wp, pb);
    round_copy<<<(Vc * Ec + 255) / 256, 256>>>(embed, embR, Vc * Ec);
    round_copy<<<(Bc * Ac + 255) / 256, 256>>>(feat, ftR, Bc * Ac);

    // init: h0 (tf32-rounded; GEMM operand next) and c0 (full fp32 state)
    {
        dim3 grid(Hc / 256, Bc / 128);   // (4, 8)
        tc_gemm<0><<<grid, 256, SMEM_BYTES>>>(ftR, Ac, Ac / 32, nullptr, 0, 0, nullptr, 0,
                                              Wih0, Ac, b_ih0, hbuf, Hc, 1,
                                              nullptr, nullptr, nullptr, nullptr);
        tc_gemm<0><<<grid, 256, SMEM_BYTES>>>(ftR, Ac, Ac / 32, nullptr, 0, 0, nullptr, 0,
                                              Wic0, Ac, b_ic0, c, Hc, 0,
                                              nullptr, nullptr, nullptr, nullptr);
    }

    // recurrence: fused gate GEMM + LSTM cell epilogue, double-buffered h
    {
        dim3 grid(Nw / 256, Bc / 128);   // (16, 8) = 128 CTAs
        for (int t = 0; t < Tc; t++) {
            float* hin  = hbuf + (size_t)(t & 1) * Bc * Hc;
            float* hout = hbuf + (size_t)((t + 1) & 1) * Bc * Hc;
            tc_gemm<1><<<grid, 256, SMEM_BYTES>>>(hin, Hc, Hc / 32, embR, Ec, Ec / 32, cap, t,
                                                  Wp, Hc + Ec, pb, nullptr, 0, 0,
                                                  cap_len, c, hout, hl);
        }
    }

    // outputs: mu, sigma2 (full-precision epilogue)
    {
        dim3 grid(Lc / 256, Bc / 128);   // (1, 8)
        tc_gemm<0><<<grid, 256, SMEM_BYTES>>>(hl, Hc, Hc / 32, nullptr, 0, 0, nullptr, 0,
                                              Wmu, Hc, b_mu, out, Lc, 0,
                                              nullptr, nullptr, nullptr, nullptr);
        tc_gemm<0><<<grid, 256, SMEM_BYTES>>>(hl, Hc, Hc / 32, nullptr, 0, 0, nullptr, 0,
                                              Ws2, Hc, b_s2, out + Bc * Lc, Lc, 0,
                                              nullptr, nullptr, nullptr, nullptr);
    }
}

// round 4
// speedup vs baseline: 3.7069x; 1.0702x over previous
#include <cuda_runtime.h>
#include <cstdint>
#include <math.h>

// ---------------- problem constants ----------------
#define Bc 1024   // batch
#define Tc 40     // timesteps
#define Ec 512    // embed dim
#define Hc 1024   // hidden
#define Lc 256    // latent out
#define Ac 2048   // feature dim
#define Vc 30000  // vocab
#define Nw 4096   // 4*H

// ---------------- device scratch (no allocation) ----------------
__device__ float g_Wcat [2 * Hc * Ac];   // [Wih0 ; Wic0] weight-normed, tf32-rounded
__device__ float g_bcat [2 * Hc];        // [b_ih0 ; b_ic0]
__device__ float g_Wocat[2 * Lc * Hc];   // [Wmu ; Ws2] weight-normed, tf32-rounded
__device__ float g_bocat[2 * Lc];        // [b_mu ; b_s2]
__device__ float g_Wp   [Nw * (Hc + Ec)];// permuted [4j+gate][W_hh | W_ih], tf32-rounded
__device__ float g_pb   [Nw];            // permuted bias b_ih+b_hh
__device__ float g_hbuf [2][Bc * Hc];    // double-buffered hidden (tf32-rounded)
__device__ float g_c    [Bc * Hc];       // cell state (full fp32)
__device__ float g_hl   [Bc * Hc];       // h at last valid step (tf32-rounded)
__device__ float g_embR [Vc * Ec];       // tf32-rounded embedding
__device__ float g_ftR  [Bc * Ac];       // tf32-rounded feat_vec

// ---------------- helpers ----------------
__device__ __forceinline__ float to_tf32(float x) {
    float r;
    asm("cvt.rna.tf32.f32 %0, %1;" : "=f"(r) : "f"(x));
    return r;
}
__device__ __forceinline__ uint32_t smem_u32(const void* p) {
    uint32_t a;
    asm("{ .reg .u64 t; cvta.to.shared.u64 t, %1; cvt.u32.u64 %0, t; }" : "=r"(a) : "l"(p));
    return a;
}
#define CP_ASYNC16(dst, src) \
    asm volatile("cp.async.cg.shared.global [%0], [%1], 16;" :: "r"(dst), "l"(src))
#define CP_COMMIT() asm volatile("cp.async.commit_group;" ::: "memory")
#define CP_WAIT2()  asm volatile("cp.async.wait_group 2;" ::: "memory")

__device__ __forceinline__ void mma_tf32(float* d, const uint32_t* a, const uint32_t* b) {
    asm volatile(
        "mma.sync.aligned.m16n8k8.row.col.f32.tf32.tf32.f32 "
        "{%0,%1,%2,%3}, {%4,%5,%6,%7}, {%8,%9}, {%0,%1,%2,%3};"
        : "+f"(d[0]), "+f"(d[1]), "+f"(d[2]), "+f"(d[3])
        : "r"(a[0]), "r"(a[1]), "r"(a[2]), "r"(a[3]), "r"(b[0]), "r"(b[1]));
}

// ---------------- prep kernels ----------------
__global__ void wn_kernel(const float* __restrict__ v, const float* __restrict__ g,
                          float* __restrict__ W, int cols) {
    int r = blockIdx.x;
    const float* vr = v + (size_t)r * cols;
    float s = 0.f;
    for (int c = threadIdx.x; c < cols; c += blockDim.x) { float x = vr[c]; s += x * x; }
    __shared__ float sh[32];
    for (int o = 16; o > 0; o >>= 1) s += __shfl_down_sync(0xffffffffu, s, o);
    if ((threadIdx.x & 31) == 0) sh[threadIdx.x >> 5] = s;
    __syncthreads();
    if (threadIdx.x < 32) {
        float t = (threadIdx.x < (blockDim.x >> 5)) ? sh[threadIdx.x] : 0.f;
        for (int o = 16; o > 0; o >>= 1) t += __shfl_down_sync(0xffffffffu, t, o);
        if (threadIdx.x == 0) sh[0] = t;
    }
    __syncthreads();
    float scale = g[r] / sqrtf(sh[0]);
    float* Wr = W + (size_t)r * cols;
    for (int c = threadIdx.x; c < cols; c += blockDim.x) Wr[c] = to_tf32(vr[c] * scale);
}

__global__ void permute_kernel(const float* __restrict__ Whh, const float* __restrict__ Wih,
                               const float* __restrict__ bih, const float* __restrict__ bhh,
                               float* __restrict__ Wp, float* __restrict__ pb) {
    int n = blockIdx.x;
    int gt = n >> 10, j = n & 1023;
    int np = (j << 2) | gt;
    float* dst = Wp + (size_t)np * (Hc + Ec);
    const float* s1 = Whh + (size_t)n * Hc;
    const float* s2 = Wih + (size_t)n * Ec;
    for (int k = threadIdx.x; k < Hc; k += blockDim.x) dst[k] = to_tf32(s1[k]);
    for (int k = threadIdx.x; k < Ec; k += blockDim.x) dst[Hc + k] = to_tf32(s2[k]);
    if (threadIdx.x == 0) pb[np] = bih[n] + bhh[n];
}

__global__ void round_copy(const float* __restrict__ src, float* __restrict__ dst, int n) {
    int i = blockIdx.x * blockDim.x + threadIdx.x;
    if (i < n) dst[i] = to_tf32(src[i]);
}

__global__ void pack2(const float* __restrict__ a, const float* __restrict__ b,
                      float* __restrict__ dst, int n) {
    int i = blockIdx.x * blockDim.x + threadIdx.x;
    if (i < n) dst[i] = a[i];
    else if (i < 2 * n) dst[i] = b[i - n];
}

// ---------------- mma.sync tf32 GEMM ----------------
// CTA tile 128(M) x NT(N), NT = NREG*32. 8 warps: 2 in M x 4 in N, warp tile 64 x NT/4.
// K in chunks of 32, 4-stage cp.async pipeline, ONE __syncthreads per chunk.
// MODE 0: C = A*W^T + bias, split at column ncut between (C1,ldc1,round1) and (C2,ldc2,round2)
// MODE 1: fused LSTM cell epilogue (N permuted 4j+gate) -> c, h, h_last
static constexpr int A_OFF = 1024;
static constexpr int A_ST  = 128 * 36 * 4;               // 18432
static constexpr int GSTRIDE = 264;                      // gate staging row stride (floats)

template <int MODE, int NREG>
__global__ __launch_bounds__(256, 1)
void tc_gemm(const float* __restrict__ A1, int lda1, int kc1,
             const float* __restrict__ A2, int lda2, int kc2,
             const int* __restrict__ cap, int t,
             const float* __restrict__ Bw, int ldb,
             const float* __restrict__ bias,
             float* __restrict__ C1, int ldc1, int round1,
             float* __restrict__ C2, int ldc2, int round2, int ncut,
             const int* __restrict__ cap_len,
             float* __restrict__ cst, float* __restrict__ hst,
             float* __restrict__ hlast)
{
    constexpr int NT   = NREG * 32;
    constexpr int B_ST = NT * 36 * 4;
    constexpr int B_OFF = A_OFF + 4 * A_ST;

    extern __shared__ __align__(1024) char smem[];
    uint32_t sb = smem_u32(smem);
    int tid = threadIdx.x, wid = tid >> 5, lid = tid & 31;
    int g = lid >> 2, tig = lid & 3;
    int warpM = (wid & 1) * 64, warpN = (wid >> 1) * (NT / 4);
    int bm = blockIdx.y * 128, bn = blockIdx.x * NT;
    const int NC = kc1 + kc2;
    int* stok = (int*)smem;

    if (kc2 > 0 && tid < 128) stok[tid] = cap[(size_t)(bm + tid) * Tc + t];
    __syncthreads();

    float acc[4][NREG][4];
#pragma unroll
    for (int i = 0; i < 4; i++)
#pragma unroll
        for (int j = 0; j < NREG; j++)
#pragma unroll
            for (int q = 0; q < 4; q++) acc[i][j][q] = 0.f;

    auto load_chunk = [&](int c, int s) {
        uint32_t aB = sb + A_OFF + s * A_ST;
        uint32_t bB = sb + B_OFF + s * B_ST;
        bool seg1 = (c < kc1);
        int kbase = seg1 ? c * 32 : (c - kc1) * 32;
#pragma unroll
        for (int i = 0; i < 4; i++) {               // A tile: 128 rows x 32 floats
            int seg = tid + i * 256;
            int m = seg >> 3, ch = seg & 7;
            const float* src = seg1
                ? (A1 + (size_t)(bm + m) * lda1 + kbase + ch * 4)
                : (A2 + (size_t)stok[m] * lda2 + kbase + ch * 4);
            CP_ASYNC16(aB + m * 144 + ch * 16, src);
        }
#pragma unroll
        for (int i = 0; i < NREG; i++) {            // B tile: NT rows x 32 floats
            int seg = tid + i * 256;
            int n = seg >> 3, ch = seg & 7;
            CP_ASYNC16(bB + n * 144 + ch * 16,
                       Bw + (size_t)(bn + n) * ldb + c * 32 + ch * 4);
        }
    };

    // prologue: fill 3 of 4 stages
    for (int p = 0; p < 3; p++) { load_chunk(p, p); CP_COMMIT(); }

    for (int c = 0; c < NC; c++) {
        int s = c & 3;
        CP_WAIT2();                 // chunk c's data resident
        __syncthreads();            // also: all reads of slot (c+3)&3 finished (iter c-1)
        if (c + 3 < NC) load_chunk(c + 3, (c + 3) & 3);
        CP_COMMIT();
        const uint32_t* aU = (const uint32_t*)(smem + A_OFF + s * A_ST);
        const uint32_t* bU = (const uint32_t*)(smem + B_OFF + s * B_ST);
#pragma unroll
        for (int kk = 0; kk < 4; kk++) {
            uint32_t afr[4][4], bfr[NREG][2];
            int kb = kk * 8 + tig;
#pragma unroll
            for (int rb = 0; rb < 4; rb++) {
                int ar = warpM + rb * 16 + g;
                afr[rb][0] = aU[ar * 36 + kb];
                afr[rb][1] = aU[(ar + 8) * 36 + kb];
                afr[rb][2] = aU[ar * 36 + kb + 4];
                afr[rb][3] = aU[(ar + 8) * 36 + kb + 4];
            }
#pragma unroll
            for (int nb = 0; nb < NREG; nb++) {
                int br = warpN + nb * 8 + g;
                bfr[nb][0] = bU[br * 36 + kb];
                bfr[nb][1] = bU[br * 36 + kb + 4];
            }
#pragma unroll
            for (int rb = 0; rb < 4; rb++)
#pragma unroll
                for (int nb = 0; nb < NREG; nb++)
                    mma_tf32(acc[rb][nb], afr[rb], bfr[nb]);
        }
    }

    // ---------------- epilogue ----------------
    if (MODE == 0) {
        float* Cd; int cb, ldc, rnd;
        if (bn < ncut) { Cd = C1; cb = bn;        ldc = ldc1; rnd = round1; }
        else           { Cd = C2; cb = bn - ncut; ldc = ldc2; rnd = round2; }
#pragma unroll
        for (int rb = 0; rb < 4; rb++) {
#pragma unroll
            for (int nb = 0; nb < NREG; nb++) {
                int coll = warpN + nb * 8 + 2 * tig;
                int col = cb + coll;
                int r0 = bm + warpM + rb * 16 + g;
                float b0 = bias[bn + coll], b1 = bias[bn + coll + 1];
                float v0 = acc[rb][nb][0] + b0, v1 = acc[rb][nb][1] + b1;
                float v2 = acc[rb][nb][2] + b0, v3 = acc[rb][nb][3] + b1;
                if (rnd) { v0 = to_tf32(v0); v1 = to_tf32(v1); v2 = to_tf32(v2); v3 = to_tf32(v3); }
                *(float2*)(Cd + (size_t)r0 * ldc + col)       = make_float2(v0, v1);
                *(float2*)(Cd + (size_t)(r0 + 8) * ldc + col) = make_float2(v2, v3);
            }
        }
    } else {
        __syncthreads();   // protect smem reuse (other warps may still read last slot)
        float* gsm = (float*)(smem + A_OFF);
#pragma unroll
        for (int rb = 0; rb < 4; rb++) {
#pragma unroll
            for (int nb = 0; nb < NREG; nb++) {
                int col = warpN + nb * 8 + 2 * tig;
                int r0 = warpM + rb * 16 + g;
                *(float2*)(gsm + r0 * GSTRIDE + col)       = make_float2(acc[rb][nb][0], acc[rb][nb][1]);
                *(float2*)(gsm + (r0 + 8) * GSTRIDE + col) = make_float2(acc[rb][nb][2], acc[rb][nb][3]);
            }
        }
        __syncthreads();
        for (int idx = tid; idx < 128 * (NT / 4); idx += 256) {
            int row = idx / (NT / 4), jl = idx % (NT / 4);
            int gm = bm + row;
            int jg = (bn >> 2) + jl;
            float4 gv = *(const float4*)(gsm + row * GSTRIDE + jl * 4);
            int nb4 = bn + jl * 4;
            float gi = gv.x + bias[nb4 + 0];
            float gf = gv.y + bias[nb4 + 1];
            float gg = gv.z + bias[nb4 + 2];
            float go = gv.w + bias[nb4 + 3];
            float si = 1.f / (1.f + expf(-gi));
            float sf = 1.f / (1.f + expf(-gf));
            float so = 1.f / (1.f + expf(-go));
            size_t off = (size_t)gm * Hc + jg;
            float cn = sf * cst[off] + si * tanhf(gg);
            float hn = to_tf32(so * tanhf(cn));
            cst[off] = cn;
            hst[off] = hn;
            if (cap_len[gm] - 1 == t) hlast[off] = hn;
        }
    }
}

// ---------------- launch ----------------
extern "C" void kernel_launch(void* const* d_in, const int* in_sizes, int n_in,
                              void* d_out, int out_size) {
    const int*   cap     = (const int*)  d_in[0];
    const int*   cap_len = (const int*)  d_in[1];
    const float* feat    = (const float*)d_in[2];
    const float* embed   = (const float*)d_in[3];
    const float* W_ih    = (const float*)d_in[4];
    const float* W_hh    = (const float*)d_in[5];
    const float* b_ih    = (const float*)d_in[6];
    const float* b_hh    = (const float*)d_in[7];
    const float* v_ih0   = (const float*)d_in[8];
    const float* g_ih0   = (const float*)d_in[9];
    const float* b_ih0   = (const float*)d_in[10];
    const float* v_ic0   = (const float*)d_in[11];
    const float* g_ic0   = (const float*)d_in[12];
    const float* b_ic0   = (const float*)d_in[13];
    const float* v_mu    = (const float*)d_in[14];
    const float* g_mu    = (const float*)d_in[15];
    const float* b_mu    = (const float*)d_in[16];
    const float* v_s2    = (const float*)d_in[17];
    const float* g_s2    = (const float*)d_in[18];
    const float* b_s2    = (const float*)d_in[19];
    float* out = (float*)d_out;

    float *Wcat, *bcat, *Wocat, *bocat, *Wp, *pb, *hbuf, *c, *hl, *embR, *ftR;
    cudaGetSymbolAddress((void**)&Wcat,  g_Wcat);
    cudaGetSymbolAddress((void**)&bcat,  g_bcat);
    cudaGetSymbolAddress((void**)&Wocat, g_Wocat);
    cudaGetSymbolAddress((void**)&bocat, g_bocat);
    cudaGetSymbolAddress((void**)&Wp,    g_Wp);
    cudaGetSymbolAddress((void**)&pb,    g_pb);
    cudaGetSymbolAddress((void**)&hbuf,  g_hbuf);
    cudaGetSymbolAddress((void**)&c,     g_c);
    cudaGetSymbolAddress((void**)&hl,    g_hl);
    cudaGetSymbolAddress((void**)&embR,  g_embR);
    cudaGetSymbolAddress((void**)&ftR,   g_ftR);

    constexpr int SMEM_8 = A_OFF + 4 * A_ST + 4 * (256 * 36 * 4);   // 222208
    constexpr int SMEM_4 = A_OFF + 4 * A_ST + 4 * (128 * 36 * 4);   // 148480
    cudaFuncSetAttribute(tc_gemm<0,4>, cudaFuncAttributeMaxDynamicSharedMemorySize, SMEM_4);
    cudaFuncSetAttribute(tc_gemm<1,8>, cudaFuncAttributeMaxDynamicSharedMemorySize, SMEM_8);

    // prep: weight norm (tf32) into concatenated buffers, permute, round activations
    wn_kernel<<<Hc, 256>>>(v_ih0, g_ih0, Wcat,            Ac);
    wn_kernel<<<Hc, 256>>>(v_ic0, g_ic0, Wcat + Hc * Ac,  Ac);
    wn_kernel<<<Lc, 256>>>(v_mu,  g_mu,  Wocat,           Hc);
    wn_kernel<<<Lc, 256>>>(v_s2,  g_s2,  Wocat + Lc * Hc, Hc);
    pack2<<<(2 * Hc + 255) / 256, 256>>>(b_ih0, b_ic0, bcat, Hc);
    pack2<<<(2 * Lc + 255) / 256, 256>>>(b_mu,  b_s2,  bocat, Lc);
    permute_kernel<<<Nw, 256>>>(W_hh, W_ih, b_ih, b_hh, Wp, pb);
    round_copy<<<(Vc * Ec + 255) / 256, 256>>>(embed, embR, Vc * Ec);
    round_copy<<<(Bc * Ac + 255) / 256, 256>>>(feat, ftR, Bc * Ac);

    // init: one fused launch -> h0 (tf32-rounded) and c0 (full fp32), N=2048, 128 CTAs
    {
        dim3 grid(2 * Hc / 128, Bc / 128);   // (16, 8)
        tc_gemm<0,4><<<grid, 256, SMEM_4>>>(ftR, Ac, Ac / 32, nullptr, 0, 0, nullptr, 0,
                                            Wcat, Ac, bcat,
                                            hbuf, Hc, 1, c, Hc, 0, Hc,
                                            nullptr, nullptr, nullptr, nullptr);
    }

    // recurrence: fused gate GEMM + LSTM cell epilogue, double-buffered h
    {
        dim3 grid(Nw / 256, Bc / 128);       // (16, 8) = 128 CTAs, one wave
        for (int t = 0; t < Tc; t++) {
            float* hin  = hbuf + (size_t)(t & 1) * Bc * Hc;
            float* hout = hbuf + (size_t)((t + 1) & 1) * Bc * Hc;
            tc_gemm<1,8><<<grid, 256, SMEM_8>>>(hin, Hc, Hc / 32, embR, Ec, Ec / 32, cap, t,
                                                Wp, Hc + Ec, pb,
                                                nullptr, 0, 0, nullptr, 0, 0, 0,
                                                cap_len, c, hout, hl);
        }
    }

    // outputs: one fused launch -> mu and sigma2, N=512, 32 CTAs
    {
        dim3 grid(2 * Lc / 128, Bc / 128);   // (4, 8)
        tc_gemm<0,4><<<grid, 256, SMEM_4>>>(hl, Hc, Hc / 32, nullptr, 0, 0, nullptr, 0,
                                            Wocat, Hc, bocat,
                                            out, Lc, 0, out + Bc * Lc, Lc, 0, Lc,
                                            nullptr, nullptr, nullptr, nullptr);
    }
}